// round 4
// baseline (speedup 1.0000x reference)
#include <cuda_runtime.h>

#define N_TRACK 50000
#define N_LANE  50000
#define N_ATT   100000
#define NP_T    1000000
#define NP_L    500000
#define E_ATT   1600000
#define HEADS   30
#define NEG_SLOPE 0.2f
#define LN_EPS  1e-5f

// ---------------- static scratch (no allocations allowed) ----------------
__device__ float g_track_pool[N_TRACK * 4];   // 0.8 MB
__device__ float g_lane_pool [N_LANE  * 2];   // 0.4 MB
__device__ float g_h         [N_ATT * 60];    // 24 MB (L2-resident in GAT phase)

// ---------------- K0: zero the pools (must happen every replay) ----------
__global__ void k_zero_pools() {
    int i = blockIdx.x * blockDim.x + threadIdx.x;
    int nt = N_TRACK * 4;
    if (i < nt) g_track_pool[i] = 0.f;
    else if (i < nt + N_LANE * 2) g_lane_pool[i - nt] = 0.f;
}

// ---------------- K1: fused point MLPs + warp-aggregated segment max ------
#define BT_BLOCKS ((NP_T + 255) / 256)
#define BL_BLOCKS ((NP_L + 255) / 256)

__global__ void __launch_bounds__(256)
k_points(const float4* __restrict__ xt, const int* __restrict__ tid,
         const float*  __restrict__ tW, const float* __restrict__ tb,
         const float*  __restrict__ tg, const float* __restrict__ tbe,
         const float2* __restrict__ xl, const int* __restrict__ lid,
         const float*  __restrict__ lW, const float* __restrict__ lb,
         const float*  __restrict__ lg, const float* __restrict__ lbe) {
    int lane = threadIdx.x & 31;
    if (blockIdx.x < BT_BLOCKS) {
        // ---- track points ----
        int i = blockIdx.x * blockDim.x + threadIdx.x;
        int t = -1;
        float v[4] = {0.f, 0.f, 0.f, 0.f};
        if (i < NP_T) {
            float4 p = xt[i];
            float h[4];
#pragma unroll
            for (int j = 0; j < 4; j++)
                h[j] = p.x * __ldg(&tW[0 * 4 + j]) + p.y * __ldg(&tW[1 * 4 + j]) +
                       p.z * __ldg(&tW[2 * 4 + j]) + p.w * __ldg(&tW[3 * 4 + j]) + __ldg(&tb[j]);
            float mu = 0.25f * (h[0] + h[1] + h[2] + h[3]);
            float var = 0.f;
#pragma unroll
            for (int j = 0; j < 4; j++) { float d = h[j] - mu; var += d * d; }
            float inv = rsqrtf(var * 0.25f + LN_EPS);
            t = tid[i];
#pragma unroll
            for (int j = 0; j < 4; j++)
                v[j] = fmaxf((h[j] - mu) * inv * __ldg(&tg[j]) + __ldg(&tbe[j]), 0.f);
        }
#pragma unroll
        for (int off = 1; off < 32; off <<= 1) {
            int t2 = __shfl_down_sync(0xffffffffu, t, off);
            float u0 = __shfl_down_sync(0xffffffffu, v[0], off);
            float u1 = __shfl_down_sync(0xffffffffu, v[1], off);
            float u2 = __shfl_down_sync(0xffffffffu, v[2], off);
            float u3 = __shfl_down_sync(0xffffffffu, v[3], off);
            if (lane + off < 32 && t2 == t) {
                v[0] = fmaxf(v[0], u0); v[1] = fmaxf(v[1], u1);
                v[2] = fmaxf(v[2], u2); v[3] = fmaxf(v[3], u3);
            }
        }
        int tprev = __shfl_up_sync(0xffffffffu, t, 1);
        bool head = (lane == 0) || (tprev != t);
        if (head && t >= 0) {
            unsigned int* pool = reinterpret_cast<unsigned int*>(&g_track_pool[t * 4]);
#pragma unroll
            for (int j = 0; j < 4; j++) atomicMax(&pool[j], __float_as_uint(v[j]));
        }
    } else {
        // ---- lane points ----
        int i = (blockIdx.x - BT_BLOCKS) * blockDim.x + threadIdx.x;
        int t = -1;
        float v0 = 0.f, v1 = 0.f;
        if (i < NP_L) {
            float2 p = xl[i];
            float h0 = p.x * __ldg(&lW[0]) + p.y * __ldg(&lW[2]) + __ldg(&lb[0]);
            float h1 = p.x * __ldg(&lW[1]) + p.y * __ldg(&lW[3]) + __ldg(&lb[1]);
            float mu = 0.5f * (h0 + h1);
            float d0 = h0 - mu, d1 = h1 - mu;
            float inv = rsqrtf(0.5f * (d0 * d0 + d1 * d1) + LN_EPS);
            t = lid[i];
            v0 = fmaxf(d0 * inv * __ldg(&lg[0]) + __ldg(&lbe[0]), 0.f);
            v1 = fmaxf(d1 * inv * __ldg(&lg[1]) + __ldg(&lbe[1]), 0.f);
        }
#pragma unroll
        for (int off = 1; off < 32; off <<= 1) {
            int t2 = __shfl_down_sync(0xffffffffu, t, off);
            float u0 = __shfl_down_sync(0xffffffffu, v0, off);
            float u1 = __shfl_down_sync(0xffffffffu, v1, off);
            if (lane + off < 32 && t2 == t) { v0 = fmaxf(v0, u0); v1 = fmaxf(v1, u1); }
        }
        int tprev = __shfl_up_sync(0xffffffffu, t, 1);
        bool head = (lane == 0) || (tprev != t);
        if (head && t >= 0) {
            unsigned int* pool = reinterpret_cast<unsigned int*>(&g_lane_pool[t * 2]);
            atomicMax(&pool[0], __float_as_uint(v0));
            atomicMax(&pool[1], __float_as_uint(v1));
        }
    }
}

// ---------------- K3: fused feats + h  (block of 256 handles 64 nodes) ----
__global__ void __launch_bounds__(256)
k_node(const float* __restrict__ tW, const float* __restrict__ tb,
       const float* __restrict__ lW, const float* __restrict__ lb,
       const float* __restrict__ fcW) {
    __shared__ float sf[64 * 10];      // feats for 64 nodes
    __shared__ float sW[10 * 60];      // gat_fc_W
    int t = threadIdx.x;
    int n0 = blockIdx.x * 64;
    for (int i = t; i < 600; i += 256) sW[i] = __ldg(&fcW[i]);
    if (t < 64) {
        int n = n0 + t;
        if (n < N_ATT) {
            if (n < N_TRACK) {
                const float* p = &g_track_pool[n * 4];
#pragma unroll
                for (int j = 0; j < 10; j++) {
                    float acc = __ldg(&tb[j]);
#pragma unroll
                    for (int k = 0; k < 4; k++) acc += p[k] * __ldg(&tW[k * 10 + j]);
                    sf[t * 10 + j] = acc;
                }
            } else {
                const float* p = &g_lane_pool[(n - N_TRACK) * 2];
#pragma unroll
                for (int j = 0; j < 10; j++) {
                    float acc = __ldg(&lb[j]);
                    acc += p[0] * __ldg(&lW[j]) + p[1] * __ldg(&lW[10 + j]);
                    sf[t * 10 + j] = acc;
                }
            }
        }
    }
    __syncthreads();
#pragma unroll
    for (int r = 0; r < 15; r++) {                     // 64*60 / 256 = 15
        int i = r * 256 + t;
        int ln = i / 60, j = i - ln * 60;
        int n = n0 + ln;
        if (n >= N_ATT) break;
        const float* f = &sf[ln * 10];
        float acc = 0.f;
#pragma unroll
        for (int k = 0; k < 10; k++) acc += f[k] * sW[k * 60 + j];
        g_h[n * 60 + j] = acc;
    }
}

// ---------------- K4: GAT — warp per dst, lane = head ---------------------
// Segment bounds via binary search on sorted att_dst (no offsets kernel).
// No max-subtraction: |el+er| << 88 so exp(v)/sum(exp) is safe in fp32.
__global__ void __launch_bounds__(256)
k_gat(const int* __restrict__ src,
      const int* __restrict__ dst,
      const float* __restrict__ al,
      const float* __restrict__ ar,
      const float* __restrict__ bias,
      float* __restrict__ out) {
    int warp = (blockIdx.x * blockDim.x + threadIdx.x) >> 5;
    int lane = threadIdx.x & 31;
    if (warp >= N_TRACK) return;           // only track destinations are output
    int d = warp;
    int hl = lane < HEADS ? lane : HEADS - 1;   // keep all 32 lanes alive for shfl

    // binary search: s0 = lower_bound(d), s1 = lower_bound(d+1)
    // uniform across the warp -> broadcast loads, top levels cache-resident
    int s0, s1;
    {
        int lo = 0, hi = E_ATT;
        while (lo < hi) { int mid = (lo + hi) >> 1; if (__ldg(&dst[mid]) < d) lo = mid + 1; else hi = mid; }
        s0 = lo;
        hi = E_ATT;
        while (lo < hi) { int mid = (lo + hi) >> 1; if (__ldg(&dst[mid]) <= d) lo = mid + 1; else hi = mid; }
        s1 = lo;
    }

    float al0 = __ldg(&al[2 * hl]), al1 = __ldg(&al[2 * hl + 1]);
    float er = g_h[d * 60 + 2 * hl]     * __ldg(&ar[2 * hl]) +
               g_h[d * 60 + 2 * hl + 1] * __ldg(&ar[2 * hl + 1]);

    float den = 0.f, acc0 = 0.f, acc1 = 0.f;

    for (int base = s0; base < s1; base += 32) {
        int cnt = s1 - base; if (cnt > 32) cnt = 32;
        int my = (lane < cnt) ? __ldg(&src[base + lane]) : 0;   // coalesced batch
        // depth-1 prefetch of h[src]
        int sp = __shfl_sync(0xffffffffu, my, 0);
        float p0 = g_h[sp * 60 + 2 * hl];
        float p1 = g_h[sp * 60 + 2 * hl + 1];
        for (int k = 0; k < cnt; k++) {
            float hs0 = p0, hs1 = p1;
            if (k + 1 < cnt) {
                int sn = __shfl_sync(0xffffffffu, my, k + 1);
                p0 = g_h[sn * 60 + 2 * hl];
                p1 = g_h[sn * 60 + 2 * hl + 1];
            }
            float v = hs0 * al0 + hs1 * al1 + er;               // el[s] + er[d]
            v = v > 0.f ? v : NEG_SLOPE * v;                    // leaky_relu
            float ee = __expf(v);
            den  += ee;
            acc0 += ee * hs0;
            acc1 += ee * hs1;
        }
    }
    if (lane < HEADS) {
        float o0, o1;
        if (s1 > s0) {
            float r = 1.f / den;
            o0 = acc0 * r + __ldg(&bias[2 * lane]);
            o1 = acc1 * r + __ldg(&bias[2 * lane + 1]);
        } else {
            o0 = __ldg(&bias[2 * lane]);
            o1 = __ldg(&bias[2 * lane + 1]);
        }
        out[d * 60 + 2 * lane]     = o0;
        out[d * 60 + 2 * lane + 1] = o1;
    }
}

// ---------------------------------------------------------------------------
extern "C" void kernel_launch(void* const* d_in, const int* in_sizes, int n_in,
                              void* d_out, int out_size) {
    const float4* track_pts = (const float4*)d_in[0];
    const float2* lane_pts  = (const float2*)d_in[1];
    const int*    pt_tid    = (const int*)d_in[2];
    const int*    pt_lid    = (const int*)d_in[3];
    const int*    att_src   = (const int*)d_in[4];
    const int*    att_dst   = (const int*)d_in[5];
    const float*  t_mlp_W   = (const float*)d_in[6];
    const float*  t_mlp_b   = (const float*)d_in[7];
    const float*  t_ln_g    = (const float*)d_in[8];
    const float*  t_ln_b    = (const float*)d_in[9];
    const float*  t_out_W   = (const float*)d_in[10];
    const float*  t_out_b   = (const float*)d_in[11];
    const float*  l_mlp_W   = (const float*)d_in[12];
    const float*  l_mlp_b   = (const float*)d_in[13];
    const float*  l_ln_g    = (const float*)d_in[14];
    const float*  l_ln_b    = (const float*)d_in[15];
    const float*  l_out_W   = (const float*)d_in[16];
    const float*  l_out_b   = (const float*)d_in[17];
    const float*  gat_fc_W  = (const float*)d_in[18];
    const float*  gat_al    = (const float*)d_in[19];
    const float*  gat_ar    = (const float*)d_in[20];
    const float*  gat_bias  = (const float*)d_in[21];
    float* out = (float*)d_out;

    const int T = 256;
    k_zero_pools<<<(N_TRACK * 4 + N_LANE * 2 + T - 1) / T, T>>>();
    k_points<<<BT_BLOCKS + BL_BLOCKS, T>>>(track_pts, pt_tid, t_mlp_W, t_mlp_b, t_ln_g, t_ln_b,
                                           lane_pts, pt_lid, l_mlp_W, l_mlp_b, l_ln_g, l_ln_b);
    k_node<<<(N_ATT + 63) / 64, T>>>(t_out_W, t_out_b, l_out_W, l_out_b, gat_fc_W);
    k_gat<<<(N_TRACK * 32 + T - 1) / T, T>>>(att_src, att_dst, gat_al, gat_ar, gat_bias, out);
}

// round 5
// speedup vs baseline: 1.5448x; 1.5448x over previous
#include <cuda_runtime.h>

#define N_TRACK 50000
#define N_LANE  50000
#define N_ATT   100000
#define NP_T    1000000
#define NP_L    500000
#define E_ATT   1600000
#define HEADS   30
#define NEG_SLOPE 0.2f
#define LN_EPS  1e-5f

// ---------------- static scratch (no allocations allowed) ----------------
__device__ float g_track_pool[N_TRACK * 4];   // 0.8 MB
__device__ float g_lane_pool [N_LANE  * 2];   // 0.4 MB
__device__ float g_h         [N_ATT * 60];    // 24 MB (L2-resident in GAT phase)
__device__ int   g_off       [N_TRACK + 1];   // CSR offsets (track dsts only)

// ---------------- K1: fused point MLPs + warp-aggregated segment max ------
#define BT_BLOCKS ((NP_T + 255) / 256)
#define BL_BLOCKS ((NP_L + 255) / 256)

__global__ void __launch_bounds__(256)
k_points(const float4* __restrict__ xt, const int* __restrict__ tid,
         const float*  __restrict__ tW, const float* __restrict__ tb,
         const float*  __restrict__ tg, const float* __restrict__ tbe,
         const float2* __restrict__ xl, const int* __restrict__ lid,
         const float*  __restrict__ lW, const float* __restrict__ lb,
         const float*  __restrict__ lg, const float* __restrict__ lbe) {
    int lane = threadIdx.x & 31;
    if (blockIdx.x < BT_BLOCKS) {
        // ---- track points ----
        int i = blockIdx.x * blockDim.x + threadIdx.x;
        int t = -1;
        float v[4] = {0.f, 0.f, 0.f, 0.f};
        if (i < NP_T) {
            float4 p = xt[i];
            float h[4];
#pragma unroll
            for (int j = 0; j < 4; j++)
                h[j] = p.x * __ldg(&tW[0 * 4 + j]) + p.y * __ldg(&tW[1 * 4 + j]) +
                       p.z * __ldg(&tW[2 * 4 + j]) + p.w * __ldg(&tW[3 * 4 + j]) + __ldg(&tb[j]);
            float mu = 0.25f * (h[0] + h[1] + h[2] + h[3]);
            float var = 0.f;
#pragma unroll
            for (int j = 0; j < 4; j++) { float d = h[j] - mu; var += d * d; }
            float inv = rsqrtf(var * 0.25f + LN_EPS);
            t = tid[i];
#pragma unroll
            for (int j = 0; j < 4; j++)
                v[j] = fmaxf((h[j] - mu) * inv * __ldg(&tg[j]) + __ldg(&tbe[j]), 0.f);
        }
#pragma unroll
        for (int off = 1; off < 32; off <<= 1) {
            int t2 = __shfl_down_sync(0xffffffffu, t, off);
            float u0 = __shfl_down_sync(0xffffffffu, v[0], off);
            float u1 = __shfl_down_sync(0xffffffffu, v[1], off);
            float u2 = __shfl_down_sync(0xffffffffu, v[2], off);
            float u3 = __shfl_down_sync(0xffffffffu, v[3], off);
            if (lane + off < 32 && t2 == t) {
                v[0] = fmaxf(v[0], u0); v[1] = fmaxf(v[1], u1);
                v[2] = fmaxf(v[2], u2); v[3] = fmaxf(v[3], u3);
            }
        }
        int tprev = __shfl_up_sync(0xffffffffu, t, 1);
        bool head = (lane == 0) || (tprev != t);
        if (head && t >= 0) {
            unsigned int* pool = reinterpret_cast<unsigned int*>(&g_track_pool[t * 4]);
#pragma unroll
            for (int j = 0; j < 4; j++) atomicMax(&pool[j], __float_as_uint(v[j]));
        }
    } else {
        // ---- lane points ----
        int i = (blockIdx.x - BT_BLOCKS) * blockDim.x + threadIdx.x;
        int t = -1;
        float v0 = 0.f, v1 = 0.f;
        if (i < NP_L) {
            float2 p = xl[i];
            float h0 = p.x * __ldg(&lW[0]) + p.y * __ldg(&lW[2]) + __ldg(&lb[0]);
            float h1 = p.x * __ldg(&lW[1]) + p.y * __ldg(&lW[3]) + __ldg(&lb[1]);
            float mu = 0.5f * (h0 + h1);
            float d0 = h0 - mu, d1 = h1 - mu;
            float inv = rsqrtf(0.5f * (d0 * d0 + d1 * d1) + LN_EPS);
            t = lid[i];
            v0 = fmaxf(d0 * inv * __ldg(&lg[0]) + __ldg(&lbe[0]), 0.f);
            v1 = fmaxf(d1 * inv * __ldg(&lg[1]) + __ldg(&lbe[1]), 0.f);
        }
#pragma unroll
        for (int off = 1; off < 32; off <<= 1) {
            int t2 = __shfl_down_sync(0xffffffffu, t, off);
            float u0 = __shfl_down_sync(0xffffffffu, v0, off);
            float u1 = __shfl_down_sync(0xffffffffu, v1, off);
            if (lane + off < 32 && t2 == t) { v0 = fmaxf(v0, u0); v1 = fmaxf(v1, u1); }
        }
        int tprev = __shfl_up_sync(0xffffffffu, t, 1);
        bool head = (lane == 0) || (tprev != t);
        if (head && t >= 0) {
            unsigned int* pool = reinterpret_cast<unsigned int*>(&g_lane_pool[t * 2]);
            atomicMax(&pool[0], __float_as_uint(v0));
            atomicMax(&pool[1], __float_as_uint(v1));
        }
    }
}

// ---------------- K_off: CSR offsets for dst < N_TRACK (int4) -------------
__global__ void k_offsets(const int* __restrict__ dst) {
    int q = blockIdx.x * blockDim.x + threadIdx.x;     // quad index
    if (q >= E_ATT / 4) return;
    int4 d4 = __ldg((const int4*)dst + q);
    if (d4.x > N_TRACK) return;          // nothing <= N_TRACK to write
    int e0 = 4 * q;
    int v[5];
    v[0] = d4.x; v[1] = d4.y; v[2] = d4.z; v[3] = d4.w;
    v[4] = (e0 + 4 < E_ATT) ? __ldg(&dst[e0 + 4]) : N_ATT;
    if (q == 0)
        for (int d = 0; d <= min(d4.x, N_TRACK); ++d) g_off[d] = 0;
#pragma unroll
    for (int k = 0; k < 4; ++k) {
        int hi = min(v[k + 1], N_TRACK);
        for (int d = v[k] + 1; d <= hi; ++d) g_off[d] = e0 + k + 1;
    }
}

// ---------------- K3: fused feats + h  (block of 256 handles 64 nodes) ----
__global__ void __launch_bounds__(256)
k_node(const float* __restrict__ tW, const float* __restrict__ tb,
       const float* __restrict__ lW, const float* __restrict__ lb,
       const float* __restrict__ fcW) {
    __shared__ float sf[64 * 10];      // feats for 64 nodes
    __shared__ float sW[10 * 60];      // gat_fc_W
    int t = threadIdx.x;
    int n0 = blockIdx.x * 64;
    for (int i = t; i < 600; i += 256) sW[i] = __ldg(&fcW[i]);
    if (t < 64) {
        int n = n0 + t;
        if (n < N_ATT) {
            if (n < N_TRACK) {
                const float* p = &g_track_pool[n * 4];
#pragma unroll
                for (int j = 0; j < 10; j++) {
                    float acc = __ldg(&tb[j]);
#pragma unroll
                    for (int k = 0; k < 4; k++) acc += p[k] * __ldg(&tW[k * 10 + j]);
                    sf[t * 10 + j] = acc;
                }
            } else {
                const float* p = &g_lane_pool[(n - N_TRACK) * 2];
#pragma unroll
                for (int j = 0; j < 10; j++) {
                    float acc = __ldg(&lb[j]);
                    acc += p[0] * __ldg(&lW[j]) + p[1] * __ldg(&lW[10 + j]);
                    sf[t * 10 + j] = acc;
                }
            }
        }
    }
    __syncthreads();
#pragma unroll
    for (int r = 0; r < 15; r++) {                     // 64*60 / 256 = 15
        int i = r * 256 + t;
        int ln = i / 60, j = i - ln * 60;
        int n = n0 + ln;
        if (n >= N_ATT) break;
        const float* f = &sf[ln * 10];
        float acc = 0.f;
#pragma unroll
        for (int k = 0; k < 10; k++) acc += f[k] * sW[k * 60 + j];
        g_h[n * 60 + j] = acc;
    }
}

// ---------------- K4: GAT — warp per dst, lane = head, float2 + x4 ILP ----
__global__ void __launch_bounds__(256)
k_gat(const int* __restrict__ src,
      const float2* __restrict__ al2,
      const float2* __restrict__ ar2,
      const float2* __restrict__ bias2,
      float2* __restrict__ out2) {
    int warp = (blockIdx.x * blockDim.x + threadIdx.x) >> 5;
    int lane = threadIdx.x & 31;
    if (warp >= N_TRACK) return;           // only track destinations are output
    int d = warp;
    int hl = lane < HEADS ? lane : HEADS - 1;   // keep all 32 lanes alive for shfl

    const float2* __restrict__ h2 = reinterpret_cast<const float2*>(g_h);

    float2 alv = __ldg(&al2[hl]);
    float2 arv = __ldg(&ar2[hl]);
    float2 hd  = h2[d * 30 + hl];
    float  er  = hd.x * arv.x + hd.y * arv.y;

    int s0 = g_off[d], s1 = g_off[d + 1];
    float den = 0.f, a0 = 0.f, a1 = 0.f;

    for (int base = s0; base < s1; base += 32) {
        int cnt = s1 - base; if (cnt > 32) cnt = 32;
        int my = (lane < cnt) ? __ldg(&src[base + lane]) : 0;   // coalesced batch
        int k = 0;
        for (; k + 4 <= cnt; k += 4) {
            int sA = __shfl_sync(0xffffffffu, my, k);
            int sB = __shfl_sync(0xffffffffu, my, k + 1);
            int sC = __shfl_sync(0xffffffffu, my, k + 2);
            int sD = __shfl_sync(0xffffffffu, my, k + 3);
            float2 hA = h2[sA * 30 + hl];                       // 4 independent LDG.64
            float2 hB = h2[sB * 30 + hl];
            float2 hC = h2[sC * 30 + hl];
            float2 hD = h2[sD * 30 + hl];
#define PROC(H) { \
            float v = fmaf((H).x, alv.x, fmaf((H).y, alv.y, er)); \
            v = v > 0.f ? v : NEG_SLOPE * v; \
            float ee = __expf(v); \
            den += ee; a0 = fmaf(ee, (H).x, a0); a1 = fmaf(ee, (H).y, a1); }
            PROC(hA) PROC(hB) PROC(hC) PROC(hD)
        }
        for (; k < cnt; ++k) {
            int s = __shfl_sync(0xffffffffu, my, k);
            float2 hS = h2[s * 30 + hl];
            PROC(hS)
        }
#undef PROC
    }
    if (lane < HEADS) {
        float2 bv = __ldg(&bias2[lane]);
        float2 o;
        if (s1 > s0) {
            float r = 1.f / den;
            o.x = fmaf(a0, r, bv.x);
            o.y = fmaf(a1, r, bv.y);
        } else {
            o = bv;
        }
        out2[d * 30 + lane] = o;
    }
}

// ---------------------------------------------------------------------------
extern "C" void kernel_launch(void* const* d_in, const int* in_sizes, int n_in,
                              void* d_out, int out_size) {
    const float4* track_pts = (const float4*)d_in[0];
    const float2* lane_pts  = (const float2*)d_in[1];
    const int*    pt_tid    = (const int*)d_in[2];
    const int*    pt_lid    = (const int*)d_in[3];
    const int*    att_src   = (const int*)d_in[4];
    const int*    att_dst   = (const int*)d_in[5];
    const float*  t_mlp_W   = (const float*)d_in[6];
    const float*  t_mlp_b   = (const float*)d_in[7];
    const float*  t_ln_g    = (const float*)d_in[8];
    const float*  t_ln_b    = (const float*)d_in[9];
    const float*  t_out_W   = (const float*)d_in[10];
    const float*  t_out_b   = (const float*)d_in[11];
    const float*  l_mlp_W   = (const float*)d_in[12];
    const float*  l_mlp_b   = (const float*)d_in[13];
    const float*  l_ln_g    = (const float*)d_in[14];
    const float*  l_ln_b    = (const float*)d_in[15];
    const float*  l_out_W   = (const float*)d_in[16];
    const float*  l_out_b   = (const float*)d_in[17];
    const float*  gat_fc_W  = (const float*)d_in[18];
    const float*  gat_al    = (const float*)d_in[19];
    const float*  gat_ar    = (const float*)d_in[20];
    const float*  gat_bias  = (const float*)d_in[21];

    // zero the segment-max pools via memset nodes (graph-capturable)
    void* p_track = nullptr; void* p_lane = nullptr;
    cudaGetSymbolAddress(&p_track, g_track_pool);
    cudaGetSymbolAddress(&p_lane,  g_lane_pool);
    cudaMemsetAsync(p_track, 0, N_TRACK * 4 * sizeof(float));
    cudaMemsetAsync(p_lane,  0, N_LANE  * 2 * sizeof(float));

    const int T = 256;
    k_points<<<BT_BLOCKS + BL_BLOCKS, T>>>(track_pts, pt_tid, t_mlp_W, t_mlp_b, t_ln_g, t_ln_b,
                                           lane_pts, pt_lid, l_mlp_W, l_mlp_b, l_ln_g, l_ln_b);
    k_offsets<<<(E_ATT / 4 + T - 1) / T, T>>>(att_dst);
    k_node<<<(N_ATT + 63) / 64, T>>>(t_out_W, t_out_b, l_out_W, l_out_b, gat_fc_W);
    k_gat<<<(N_TRACK * 32 + T - 1) / T, T>>>(att_src,
                                             (const float2*)gat_al,
                                             (const float2*)gat_ar,
                                             (const float2*)gat_bias,
                                             (float2*)d_out);
}

// round 6
// speedup vs baseline: 1.5795x; 1.0225x over previous
#include <cuda_runtime.h>

#define N_TRACK 50000
#define N_LANE  50000
#define N_ATT   100000
#define NP_T    1000000
#define NP_L    500000
#define E_ATT   1600000
#define HEADS   30
#define NEG_SLOPE 0.2f
#define LN_EPS  1e-5f
#define LOG2E   1.4426950408889634f

// ---------------- static scratch (no allocations allowed) ----------------
__device__ float g_track_pool[N_TRACK * 4];   // 0.8 MB
__device__ float g_lane_pool [N_LANE  * 2];   // 0.4 MB
__device__ float g_h         [N_ATT * 60];    // 24 MB (L2-resident in GAT phase)
__device__ int   g_off       [N_TRACK + 1];   // CSR offsets (track dsts only)

__device__ __forceinline__ float ex2f(float x) {
    float r; asm("ex2.approx.ftz.f32 %0, %1;" : "=f"(r) : "f"(x)); return r;
}

// ---------------- K1: fused point MLPs + segment max + CSR offsets --------
#define BT_BLOCKS  ((NP_T + 255) / 256)
#define BL_BLOCKS  ((NP_L + 255) / 256)
#define OFF_BLOCKS ((E_ATT / 4 + 255) / 256)

__global__ void __launch_bounds__(256)
k_points(const float4* __restrict__ xt, const int* __restrict__ tid,
         const float*  __restrict__ tW, const float* __restrict__ tb,
         const float*  __restrict__ tg, const float* __restrict__ tbe,
         const float2* __restrict__ xl, const int* __restrict__ lid,
         const float*  __restrict__ lW, const float* __restrict__ lb,
         const float*  __restrict__ lg, const float* __restrict__ lbe,
         const int*    __restrict__ dst) {
    int lane = threadIdx.x & 31;
    if (blockIdx.x < BT_BLOCKS) {
        // ---- track points ----
        int i = blockIdx.x * blockDim.x + threadIdx.x;
        int t = -1;
        float v[4] = {0.f, 0.f, 0.f, 0.f};
        if (i < NP_T) {
            float4 p = xt[i];
            float h[4];
#pragma unroll
            for (int j = 0; j < 4; j++)
                h[j] = p.x * __ldg(&tW[0 * 4 + j]) + p.y * __ldg(&tW[1 * 4 + j]) +
                       p.z * __ldg(&tW[2 * 4 + j]) + p.w * __ldg(&tW[3 * 4 + j]) + __ldg(&tb[j]);
            float mu = 0.25f * (h[0] + h[1] + h[2] + h[3]);
            float var = 0.f;
#pragma unroll
            for (int j = 0; j < 4; j++) { float d = h[j] - mu; var += d * d; }
            float inv = rsqrtf(var * 0.25f + LN_EPS);
            t = tid[i];
#pragma unroll
            for (int j = 0; j < 4; j++)
                v[j] = fmaxf((h[j] - mu) * inv * __ldg(&tg[j]) + __ldg(&tbe[j]), 0.f);
        }
        // HW-aggregated segmented max: lanes with equal id share one reduction
        unsigned msk = __match_any_sync(0xffffffffu, t);
        unsigned r0 = __reduce_max_sync(msk, __float_as_uint(v[0]));
        unsigned r1 = __reduce_max_sync(msk, __float_as_uint(v[1]));
        unsigned r2 = __reduce_max_sync(msk, __float_as_uint(v[2]));
        unsigned r3 = __reduce_max_sync(msk, __float_as_uint(v[3]));
        if (t >= 0 && lane == (__ffs(msk) - 1)) {
            unsigned int* pool = reinterpret_cast<unsigned int*>(&g_track_pool[t * 4]);
            atomicMax(&pool[0], r0); atomicMax(&pool[1], r1);
            atomicMax(&pool[2], r2); atomicMax(&pool[3], r3);
        }
    } else if (blockIdx.x < BT_BLOCKS + BL_BLOCKS) {
        // ---- lane points ----
        int i = (blockIdx.x - BT_BLOCKS) * blockDim.x + threadIdx.x;
        int t = -1;
        float v0 = 0.f, v1 = 0.f;
        if (i < NP_L) {
            float2 p = xl[i];
            float h0 = p.x * __ldg(&lW[0]) + p.y * __ldg(&lW[2]) + __ldg(&lb[0]);
            float h1 = p.x * __ldg(&lW[1]) + p.y * __ldg(&lW[3]) + __ldg(&lb[1]);
            float mu = 0.5f * (h0 + h1);
            float d0 = h0 - mu, d1 = h1 - mu;
            float inv = rsqrtf(0.5f * (d0 * d0 + d1 * d1) + LN_EPS);
            t = lid[i];
            v0 = fmaxf(d0 * inv * __ldg(&lg[0]) + __ldg(&lbe[0]), 0.f);
            v1 = fmaxf(d1 * inv * __ldg(&lg[1]) + __ldg(&lbe[1]), 0.f);
        }
        unsigned msk = __match_any_sync(0xffffffffu, t);
        unsigned r0 = __reduce_max_sync(msk, __float_as_uint(v0));
        unsigned r1 = __reduce_max_sync(msk, __float_as_uint(v1));
        if (t >= 0 && lane == (__ffs(msk) - 1)) {
            unsigned int* pool = reinterpret_cast<unsigned int*>(&g_lane_pool[t * 2]);
            atomicMax(&pool[0], r0); atomicMax(&pool[1], r1);
        }
    } else {
        // ---- CSR offsets for dst < N_TRACK (int4) ----
        int q = (blockIdx.x - BT_BLOCKS - BL_BLOCKS) * blockDim.x + threadIdx.x;
        if (q >= E_ATT / 4) return;
        int4 d4 = __ldg((const int4*)dst + q);
        int e0 = 4 * q;
        if (q == 0)
            for (int d = 0; d <= min(d4.x, N_TRACK); ++d) g_off[d] = 0;
        if (d4.x > N_TRACK) return;          // nothing <= N_TRACK left to write
        int v[5];
        v[0] = d4.x; v[1] = d4.y; v[2] = d4.z; v[3] = d4.w;
        v[4] = (e0 + 4 < E_ATT) ? __ldg(&dst[e0 + 4]) : N_ATT;
#pragma unroll
        for (int k = 0; k < 4; ++k) {
            int hi = min(v[k + 1], N_TRACK);
            for (int d = v[k] + 1; d <= hi; ++d) g_off[d] = e0 + k + 1;
        }
    }
}

// ---------------- K3: fused feats + h  (block of 256 handles 64 nodes) ----
__global__ void __launch_bounds__(256)
k_node(const float* __restrict__ tW, const float* __restrict__ tb,
       const float* __restrict__ lW, const float* __restrict__ lb,
       const float* __restrict__ fcW) {
    __shared__ float sf[64 * 10];      // feats for 64 nodes
    __shared__ float sW[10 * 60];      // gat_fc_W
    int t = threadIdx.x;
    int n0 = blockIdx.x * 64;
    for (int i = t; i < 600; i += 256) sW[i] = __ldg(&fcW[i]);
    // feats: 640 items over 256 threads
#pragma unroll
    for (int r = 0; r < 3; r++) {
        int idx = r * 256 + t;
        if (idx >= 640) break;
        int ln = idx / 10, j = idx - ln * 10;
        int n = n0 + ln;
        if (n >= N_ATT) break;
        float acc;
        if (n < N_TRACK) {
            const float* p = &g_track_pool[n * 4];
            acc = __ldg(&tb[j]);
#pragma unroll
            for (int k = 0; k < 4; k++) acc += p[k] * __ldg(&tW[k * 10 + j]);
        } else {
            const float* p = &g_lane_pool[(n - N_TRACK) * 2];
            acc = __ldg(&lb[j]) + p[0] * __ldg(&lW[j]) + p[1] * __ldg(&lW[10 + j]);
        }
        sf[ln * 10 + j] = acc;
    }
    __syncthreads();
    // h: 64 nodes x 30 float2-pairs = 1920 items
    float2* __restrict__ h2 = reinterpret_cast<float2*>(g_h);
#pragma unroll
    for (int r = 0; r < 8; r++) {
        int idx = r * 256 + t;
        if (idx >= 1920) break;
        int ln = idx / 30, jp = idx - ln * 30;
        int n = n0 + ln;
        if (n >= N_ATT) break;
        const float* f = &sf[ln * 10];
        float a0 = 0.f, a1 = 0.f;
#pragma unroll
        for (int k = 0; k < 10; k++) {
            a0 = fmaf(f[k], sW[k * 60 + 2 * jp],     a0);
            a1 = fmaf(f[k], sW[k * 60 + 2 * jp + 1], a1);
        }
        h2[n * 30 + jp] = make_float2(a0, a1);
    }
}

// ---------------- K4: GAT — warp per dst, lane = head, float2 + x4 ILP ----
// attn weights prescaled by log2(e): leaky is scale-equivariant, so
// ex2(leaky(log2e*v)) == exp(leaky(v)); one MUFU per edge, no FMUL.
__global__ void __launch_bounds__(256)
k_gat(const int* __restrict__ src,
      const float2* __restrict__ al2,
      const float2* __restrict__ ar2,
      const float2* __restrict__ bias2,
      float2* __restrict__ out2) {
    int warp = (blockIdx.x * blockDim.x + threadIdx.x) >> 5;
    int lane = threadIdx.x & 31;
    if (warp >= N_TRACK) return;           // only track destinations are output
    int d = warp;
    int hl = lane < HEADS ? lane : HEADS - 1;   // keep all 32 lanes alive for shfl

    const float2* __restrict__ h2 = reinterpret_cast<const float2*>(g_h);

    float2 alv = __ldg(&al2[hl]);  alv.x *= LOG2E; alv.y *= LOG2E;
    float2 arv = __ldg(&ar2[hl]);
    float2 hd  = h2[d * 30 + hl];
    float  er  = LOG2E * (hd.x * arv.x + hd.y * arv.y);

    int s0 = g_off[d], s1 = g_off[d + 1];
    float den = 0.f, a0 = 0.f, a1 = 0.f;

    for (int base = s0; base < s1; base += 32) {
        int cnt = s1 - base; if (cnt > 32) cnt = 32;
        int my = (lane < cnt) ? __ldg(&src[base + lane]) : 0;   // coalesced batch
        int k = 0;
        for (; k + 4 <= cnt; k += 4) {
            int sA = __shfl_sync(0xffffffffu, my, k);
            int sB = __shfl_sync(0xffffffffu, my, k + 1);
            int sC = __shfl_sync(0xffffffffu, my, k + 2);
            int sD = __shfl_sync(0xffffffffu, my, k + 3);
            float2 hA = h2[sA * 30 + hl];                       // 4 independent LDG.64
            float2 hB = h2[sB * 30 + hl];
            float2 hC = h2[sC * 30 + hl];
            float2 hD = h2[sD * 30 + hl];
#define PROC(H) { \
            float v = fmaf((H).x, alv.x, fmaf((H).y, alv.y, er)); \
            v = fmaxf(v, NEG_SLOPE * v); \
            float ee = ex2f(v); \
            den += ee; a0 = fmaf(ee, (H).x, a0); a1 = fmaf(ee, (H).y, a1); }
            PROC(hA) PROC(hB) PROC(hC) PROC(hD)
        }
        for (; k < cnt; ++k) {
            int s = __shfl_sync(0xffffffffu, my, k);
            float2 hS = h2[s * 30 + hl];
            PROC(hS)
        }
#undef PROC
    }
    if (lane < HEADS) {
        float2 bv = __ldg(&bias2[lane]);
        float2 o;
        if (s1 > s0) {
            float r = 1.f / den;
            o.x = fmaf(a0, r, bv.x);
            o.y = fmaf(a1, r, bv.y);
        } else {
            o = bv;
        }
        out2[d * 30 + lane] = o;
    }
}

// ---------------------------------------------------------------------------
extern "C" void kernel_launch(void* const* d_in, const int* in_sizes, int n_in,
                              void* d_out, int out_size) {
    const float4* track_pts = (const float4*)d_in[0];
    const float2* lane_pts  = (const float2*)d_in[1];
    const int*    pt_tid    = (const int*)d_in[2];
    const int*    pt_lid    = (const int*)d_in[3];
    const int*    att_src   = (const int*)d_in[4];
    const int*    att_dst   = (const int*)d_in[5];
    const float*  t_mlp_W   = (const float*)d_in[6];
    const float*  t_mlp_b   = (const float*)d_in[7];
    const float*  t_ln_g    = (const float*)d_in[8];
    const float*  t_ln_b    = (const float*)d_in[9];
    const float*  t_out_W   = (const float*)d_in[10];
    const float*  t_out_b   = (const float*)d_in[11];
    const float*  l_mlp_W   = (const float*)d_in[12];
    const float*  l_mlp_b   = (const float*)d_in[13];
    const float*  l_ln_g    = (const float*)d_in[14];
    const float*  l_ln_b    = (const float*)d_in[15];
    const float*  l_out_W   = (const float*)d_in[16];
    const float*  l_out_b   = (const float*)d_in[17];
    const float*  gat_fc_W  = (const float*)d_in[18];
    const float*  gat_al    = (const float*)d_in[19];
    const float*  gat_ar    = (const float*)d_in[20];
    const float*  gat_bias  = (const float*)d_in[21];

    // zero the segment-max pools (graph-capturable memset nodes)
    void* p_track = nullptr; void* p_lane = nullptr;
    cudaGetSymbolAddress(&p_track, g_track_pool);
    cudaGetSymbolAddress(&p_lane,  g_lane_pool);
    cudaMemsetAsync(p_track, 0, N_TRACK * 4 * sizeof(float));
    cudaMemsetAsync(p_lane,  0, N_LANE  * 2 * sizeof(float));

    const int T = 256;
    k_points<<<BT_BLOCKS + BL_BLOCKS + OFF_BLOCKS, T>>>(
        track_pts, pt_tid, t_mlp_W, t_mlp_b, t_ln_g, t_ln_b,
        lane_pts, pt_lid, l_mlp_W, l_mlp_b, l_ln_g, l_ln_b,
        att_dst);
    k_node<<<(N_ATT + 63) / 64, T>>>(t_out_W, t_out_b, l_out_W, l_out_b, gat_fc_W);
    k_gat<<<(N_TRACK * 32 + T - 1) / T, T>>>(att_src,
                                             (const float2*)gat_al,
                                             (const float2*)gat_ar,
                                             (const float2*)gat_bias,
                                             (float2*)d_out);
}

// round 7
// speedup vs baseline: 1.5950x; 1.0098x over previous
#include <cuda_runtime.h>

#define N_TRACK 50000
#define N_LANE  50000
#define N_ATT   100000
#define NP_T    1000000
#define NP_L    500000
#define E_ATT   1600000
#define HEADS   30
#define NEG_SLOPE 0.2f
#define LN_EPS  1e-5f
#define LOG2E   1.4426950408889634f

// ---------------- static scratch (no allocations allowed) ----------------
__device__ float g_track_pool[N_TRACK * 4];   // 0.8 MB
__device__ float g_lane_pool [N_LANE  * 2];   // 0.4 MB
__device__ float g_h         [N_ATT * 60];    // 24 MB (L2-resident in GAT phase)
__device__ int   g_off       [N_TRACK + 1];   // CSR offsets (track dsts only)

__device__ __forceinline__ float ex2f(float x) {
    float r; asm("ex2.approx.ftz.f32 %0, %1;" : "=f"(r) : "f"(x)); return r;
}

// ---------------- K1: fused point MLPs (4 pts/thread) + segmax + offsets --
#define BT_BLOCKS  ((NP_T / 4 + 255) / 256)
#define BL_BLOCKS  ((NP_L / 4 + 255) / 256)
#define OFF_BLOCKS ((E_ATT / 4 + 255) / 256)

__global__ void __launch_bounds__(256)
k_points(const float4* __restrict__ xt, const int* __restrict__ tid,
         const float*  __restrict__ tW, const float* __restrict__ tb,
         const float*  __restrict__ tg, const float* __restrict__ tbe,
         const float4* __restrict__ xl4, const int* __restrict__ lid,
         const float*  __restrict__ lW, const float* __restrict__ lb,
         const float*  __restrict__ lg, const float* __restrict__ lbe,
         const int*    __restrict__ dst) {
    int lane = threadIdx.x & 31;
    if (blockIdx.x < BT_BLOCKS) {
        // ---- track points: thread q handles points 4q..4q+3 ----
        int q = blockIdx.x * blockDim.x + threadIdx.x;
        int ids[4] = {-1, -1, -1, -1};
        float v[4][4];
#pragma unroll
        for (int j = 0; j < 4; j++)
#pragma unroll
            for (int c = 0; c < 4; c++) v[j][c] = 0.f;
        if (q < NP_T / 4) {
            int4 tt = __ldg((const int4*)tid + q);
            ids[0] = tt.x; ids[1] = tt.y; ids[2] = tt.z; ids[3] = tt.w;
            float4 p[4];
#pragma unroll
            for (int j = 0; j < 4; j++) p[j] = xt[4 * q + j];
#pragma unroll
            for (int j = 0; j < 4; j++) {
                float h[4];
#pragma unroll
                for (int c = 0; c < 4; c++)
                    h[c] = p[j].x * __ldg(&tW[0 * 4 + c]) + p[j].y * __ldg(&tW[1 * 4 + c]) +
                           p[j].z * __ldg(&tW[2 * 4 + c]) + p[j].w * __ldg(&tW[3 * 4 + c]) + __ldg(&tb[c]);
                float mu = 0.25f * (h[0] + h[1] + h[2] + h[3]);
                float var = 0.f;
#pragma unroll
                for (int c = 0; c < 4; c++) { float d = h[c] - mu; var += d * d; }
                float inv = rsqrtf(var * 0.25f + LN_EPS);
#pragma unroll
                for (int c = 0; c < 4; c++)
                    v[j][c] = fmaxf((h[c] - mu) * inv * __ldg(&tg[c]) + __ldg(&tbe[c]), 0.f);
            }
        }
        // in-thread merge of adjacent equal ids (sorted input)
#pragma unroll
        for (int j = 3; j >= 1; j--) {
            if (ids[j] == ids[j - 1]) {
#pragma unroll
                for (int c = 0; c < 4; c++) v[j - 1][c] = fmaxf(v[j - 1][c], v[j][c]);
                ids[j] = -1;
            }
        }
        // per-slot warp aggregation (HW match + redux)
#pragma unroll
        for (int j = 0; j < 4; j++) {
            unsigned msk = __match_any_sync(0xffffffffu, ids[j]);
            unsigned r0 = __reduce_max_sync(msk, __float_as_uint(v[j][0]));
            unsigned r1 = __reduce_max_sync(msk, __float_as_uint(v[j][1]));
            unsigned r2 = __reduce_max_sync(msk, __float_as_uint(v[j][2]));
            unsigned r3 = __reduce_max_sync(msk, __float_as_uint(v[j][3]));
            if (ids[j] >= 0 && lane == (__ffs(msk) - 1)) {
                unsigned int* pool = reinterpret_cast<unsigned int*>(&g_track_pool[ids[j] * 4]);
                atomicMax(&pool[0], r0); atomicMax(&pool[1], r1);
                atomicMax(&pool[2], r2); atomicMax(&pool[3], r3);
            }
        }
    } else if (blockIdx.x < BT_BLOCKS + BL_BLOCKS) {
        // ---- lane points: thread q handles points 4q..4q+3 ----
        int q = (blockIdx.x - BT_BLOCKS) * blockDim.x + threadIdx.x;
        int ids[4] = {-1, -1, -1, -1};
        float v0[4] = {0.f, 0.f, 0.f, 0.f}, v1[4] = {0.f, 0.f, 0.f, 0.f};
        if (q < NP_L / 4) {
            int4 tt = __ldg((const int4*)lid + q);
            ids[0] = tt.x; ids[1] = tt.y; ids[2] = tt.z; ids[3] = tt.w;
            float4 pa = xl4[2 * q], pb = xl4[2 * q + 1];
            float px[4] = {pa.x, pa.z, pb.x, pb.z};
            float py[4] = {pa.y, pa.w, pb.y, pb.w};
#pragma unroll
            for (int j = 0; j < 4; j++) {
                float h0 = px[j] * __ldg(&lW[0]) + py[j] * __ldg(&lW[2]) + __ldg(&lb[0]);
                float h1 = px[j] * __ldg(&lW[1]) + py[j] * __ldg(&lW[3]) + __ldg(&lb[1]);
                float mu = 0.5f * (h0 + h1);
                float d0 = h0 - mu, d1 = h1 - mu;
                float inv = rsqrtf(0.5f * (d0 * d0 + d1 * d1) + LN_EPS);
                v0[j] = fmaxf(d0 * inv * __ldg(&lg[0]) + __ldg(&lbe[0]), 0.f);
                v1[j] = fmaxf(d1 * inv * __ldg(&lg[1]) + __ldg(&lbe[1]), 0.f);
            }
        }
#pragma unroll
        for (int j = 3; j >= 1; j--) {
            if (ids[j] == ids[j - 1]) {
                v0[j - 1] = fmaxf(v0[j - 1], v0[j]);
                v1[j - 1] = fmaxf(v1[j - 1], v1[j]);
                ids[j] = -1;
            }
        }
#pragma unroll
        for (int j = 0; j < 4; j++) {
            unsigned msk = __match_any_sync(0xffffffffu, ids[j]);
            unsigned r0 = __reduce_max_sync(msk, __float_as_uint(v0[j]));
            unsigned r1 = __reduce_max_sync(msk, __float_as_uint(v1[j]));
            if (ids[j] >= 0 && lane == (__ffs(msk) - 1)) {
                unsigned int* pool = reinterpret_cast<unsigned int*>(&g_lane_pool[ids[j] * 2]);
                atomicMax(&pool[0], r0); atomicMax(&pool[1], r1);
            }
        }
    } else {
        // ---- CSR offsets for dst < N_TRACK (int4) ----
        int q = (blockIdx.x - BT_BLOCKS - BL_BLOCKS) * blockDim.x + threadIdx.x;
        if (q >= E_ATT / 4) return;
        int4 d4 = __ldg((const int4*)dst + q);
        int e0 = 4 * q;
        if (q == 0)
            for (int d = 0; d <= min(d4.x, N_TRACK); ++d) g_off[d] = 0;
        if (d4.x > N_TRACK) return;          // nothing <= N_TRACK left to write
        int v[5];
        v[0] = d4.x; v[1] = d4.y; v[2] = d4.z; v[3] = d4.w;
        v[4] = (e0 + 4 < E_ATT) ? __ldg(&dst[e0 + 4]) : N_ATT;
#pragma unroll
        for (int k = 0; k < 4; ++k) {
            int hi = min(v[k + 1], N_TRACK);
            for (int d = v[k] + 1; d <= hi; ++d) g_off[d] = e0 + k + 1;
        }
    }
}

// ---------------- K3: fused feats + h  (block of 256 handles 64 nodes) ----
__global__ void __launch_bounds__(256)
k_node(const float* __restrict__ tW, const float* __restrict__ tb,
       const float* __restrict__ lW, const float* __restrict__ lb,
       const float* __restrict__ fcW) {
    __shared__ float sf[64 * 10];      // feats for 64 nodes
    __shared__ float sW[10 * 60];      // gat_fc_W
    int t = threadIdx.x;
    int n0 = blockIdx.x * 64;
    for (int i = t; i < 600; i += 256) sW[i] = __ldg(&fcW[i]);
    // feats: 640 items over 256 threads
#pragma unroll
    for (int r = 0; r < 3; r++) {
        int idx = r * 256 + t;
        if (idx >= 640) break;
        int ln = idx / 10, j = idx - ln * 10;
        int n = n0 + ln;
        if (n >= N_ATT) break;
        float acc;
        if (n < N_TRACK) {
            const float* p = &g_track_pool[n * 4];
            acc = __ldg(&tb[j]);
#pragma unroll
            for (int k = 0; k < 4; k++) acc += p[k] * __ldg(&tW[k * 10 + j]);
        } else {
            const float* p = &g_lane_pool[(n - N_TRACK) * 2];
            acc = __ldg(&lb[j]) + p[0] * __ldg(&lW[j]) + p[1] * __ldg(&lW[10 + j]);
        }
        sf[ln * 10 + j] = acc;
    }
    __syncthreads();
    // h: 64 nodes x 15 float4 = 960 items
    float4* __restrict__ h4 = reinterpret_cast<float4*>(g_h);
#pragma unroll
    for (int r = 0; r < 4; r++) {
        int idx = r * 256 + t;
        if (idx >= 960) break;
        int ln = idx / 15, qp = idx - ln * 15;
        int n = n0 + ln;
        if (n >= N_ATT) break;
        const float* f = &sf[ln * 10];
        float4 a = make_float4(0.f, 0.f, 0.f, 0.f);
#pragma unroll
        for (int k = 0; k < 10; k++) {
            float fk = f[k];
            const float* w = &sW[k * 60 + 4 * qp];
            a.x = fmaf(fk, w[0], a.x);
            a.y = fmaf(fk, w[1], a.y);
            a.z = fmaf(fk, w[2], a.z);
            a.w = fmaf(fk, w[3], a.w);
        }
        h4[n * 15 + qp] = a;
    }
}

// ---------------- K4: GAT — warp per dst, lane = head, float2 + x4 ILP ----
// attn weights prescaled by log2(e): leaky is scale-equivariant, so
// ex2(leaky(log2e*v)) == exp(leaky(v)); one MUFU per edge.
__global__ void __launch_bounds__(256)
k_gat(const int* __restrict__ src,
      const float2* __restrict__ al2,
      const float2* __restrict__ ar2,
      const float2* __restrict__ bias2,
      float2* __restrict__ out2) {
    int warp = (blockIdx.x * blockDim.x + threadIdx.x) >> 5;
    int lane = threadIdx.x & 31;
    if (warp >= N_TRACK) return;           // only track destinations are output
    int d = warp;
    int hl = lane < HEADS ? lane : HEADS - 1;   // keep all 32 lanes alive for shfl

    const float2* __restrict__ h2 = reinterpret_cast<const float2*>(g_h);

    float2 alv = __ldg(&al2[hl]);  alv.x *= LOG2E; alv.y *= LOG2E;
    float2 arv = __ldg(&ar2[hl]);
    float2 hd  = h2[d * 30 + hl];
    float  er  = LOG2E * (hd.x * arv.x + hd.y * arv.y);

    int s0 = g_off[d], s1 = g_off[d + 1];
    float den = 0.f, a0 = 0.f, a1 = 0.f;

#define PROC(H) { \
    float v = fmaf((H).x, alv.x, fmaf((H).y, alv.y, er)); \
    v = fmaxf(v, NEG_SLOPE * v); \
    float ee = ex2f(v); \
    den += ee; a0 = fmaf(ee, (H).x, a0); a1 = fmaf(ee, (H).y, a1); }
#define PROCM(H, pred) { \
    float v = fmaf((H).x, alv.x, fmaf((H).y, alv.y, er)); \
    v = fmaxf(v, NEG_SLOPE * v); \
    float ee = (pred) ? ex2f(v) : 0.f; \
    den += ee; a0 = fmaf(ee, (H).x, a0); a1 = fmaf(ee, (H).y, a1); }

    for (int base = s0; base < s1; base += 32) {
        int cnt = s1 - base; if (cnt > 32) cnt = 32;
        int my = (lane < cnt) ? __ldg(&src[base + lane]) : 0;   // coalesced batch
        int k = 0;
        for (; k + 4 <= cnt; k += 4) {
            int sA = __shfl_sync(0xffffffffu, my, k);
            int sB = __shfl_sync(0xffffffffu, my, k + 1);
            int sC = __shfl_sync(0xffffffffu, my, k + 2);
            int sD = __shfl_sync(0xffffffffu, my, k + 3);
            float2 hA = h2[sA * 30 + hl];                       // 4 independent LDG.64
            float2 hB = h2[sB * 30 + hl];
            float2 hC = h2[sC * 30 + hl];
            float2 hD = h2[sD * 30 + hl];
            PROC(hA) PROC(hB) PROC(hC) PROC(hD)
        }
        if (k < cnt) {                                          // masked tail group
            int last = cnt - 1;
            int sA = __shfl_sync(0xffffffffu, my, k);
            int sB = __shfl_sync(0xffffffffu, my, min(k + 1, last));
            int sC = __shfl_sync(0xffffffffu, my, min(k + 2, last));
            float2 hA = h2[sA * 30 + hl];
            float2 hB = h2[sB * 30 + hl];
            float2 hC = h2[sC * 30 + hl];
            PROC(hA)
            PROCM(hB, k + 1 < cnt)
            PROCM(hC, k + 2 < cnt)
        }
    }
#undef PROC
#undef PROCM
    if (lane < HEADS) {
        float2 bv = __ldg(&bias2[lane]);
        float2 o;
        if (s1 > s0) {
            float r = 1.f / den;
            o.x = fmaf(a0, r, bv.x);
            o.y = fmaf(a1, r, bv.y);
        } else {
            o = bv;
        }
        out2[d * 30 + lane] = o;
    }
}

// ---------------------------------------------------------------------------
extern "C" void kernel_launch(void* const* d_in, const int* in_sizes, int n_in,
                              void* d_out, int out_size) {
    const float4* track_pts = (const float4*)d_in[0];
    const float4* lane_pts4 = (const float4*)d_in[1];
    const int*    pt_tid    = (const int*)d_in[2];
    const int*    pt_lid    = (const int*)d_in[3];
    const int*    att_src   = (const int*)d_in[4];
    const int*    att_dst   = (const int*)d_in[5];
    const float*  t_mlp_W   = (const float*)d_in[6];
    const float*  t_mlp_b   = (const float*)d_in[7];
    const float*  t_ln_g    = (const float*)d_in[8];
    const float*  t_ln_b    = (const float*)d_in[9];
    const float*  t_out_W   = (const float*)d_in[10];
    const float*  t_out_b   = (const float*)d_in[11];
    const float*  l_mlp_W   = (const float*)d_in[12];
    const float*  l_mlp_b   = (const float*)d_in[13];
    const float*  l_ln_g    = (const float*)d_in[14];
    const float*  l_ln_b    = (const float*)d_in[15];
    const float*  l_out_W   = (const float*)d_in[16];
    const float*  l_out_b   = (const float*)d_in[17];
    const float*  gat_fc_W  = (const float*)d_in[18];
    const float*  gat_al    = (const float*)d_in[19];
    const float*  gat_ar    = (const float*)d_in[20];
    const float*  gat_bias  = (const float*)d_in[21];

    // zero the segment-max pools (graph-capturable memset nodes)
    void* p_track = nullptr; void* p_lane = nullptr;
    cudaGetSymbolAddress(&p_track, g_track_pool);
    cudaGetSymbolAddress(&p_lane,  g_lane_pool);
    cudaMemsetAsync(p_track, 0, N_TRACK * 4 * sizeof(float));
    cudaMemsetAsync(p_lane,  0, N_LANE  * 2 * sizeof(float));

    const int T = 256;
    k_points<<<BT_BLOCKS + BL_BLOCKS + OFF_BLOCKS, T>>>(
        track_pts, pt_tid, t_mlp_W, t_mlp_b, t_ln_g, t_ln_b,
        lane_pts4, pt_lid, l_mlp_W, l_mlp_b, l_ln_g, l_ln_b,
        att_dst);
    k_node<<<(N_ATT + 63) / 64, T>>>(t_out_W, t_out_b, l_out_W, l_out_b, gat_fc_W);
    k_gat<<<(N_TRACK * 32 + T - 1) / T, T>>>(att_src,
                                             (const float2*)gat_al,
                                             (const float2*)gat_ar,
                                             (const float2*)gat_bias,
                                             (float2*)d_out);
}

// round 8
// speedup vs baseline: 1.7089x; 1.0714x over previous
#include <cuda_runtime.h>

#define N_TRACK 50000
#define N_LANE  50000
#define N_ATT   100000
#define NP_T    1000000
#define NP_L    500000
#define E_ATT   1600000
#define HEADS   30
#define NEG_SLOPE 0.2f
#define LN_EPS  1e-5f
#define LOG2E   1.4426950408889634f

// ---------------- static scratch (no allocations allowed) ----------------
__device__ float g_track_pool[N_TRACK * 4];   // 0.8 MB
__device__ float g_lane_pool [N_LANE  * 2];   // 0.4 MB
__device__ float g_h         [N_ATT * 60];    // 24 MB (L2-resident in GAT phase)
__device__ int   g_off       [N_TRACK + 1];   // CSR offsets (track dsts only)

__device__ __forceinline__ float ex2f(float x) {
    float r; asm("ex2.approx.ftz.f32 %0, %1;" : "=f"(r) : "f"(x)); return r;
}

// ---------------- K1: fused point MLPs (2 pts/thread) + segmax + offsets --
#define BT_BLOCKS  ((NP_T / 2 + 255) / 256)
#define BL_BLOCKS  ((NP_L / 2 + 255) / 256)
#define OFF_BLOCKS ((E_ATT / 4 + 255) / 256)

__global__ void __launch_bounds__(256)
k_points(const float4* __restrict__ xt, const int* __restrict__ tid,
         const float*  __restrict__ tW, const float* __restrict__ tb,
         const float*  __restrict__ tg, const float* __restrict__ tbe,
         const float4* __restrict__ xl4, const int* __restrict__ lid,
         const float*  __restrict__ lW, const float* __restrict__ lb,
         const float*  __restrict__ lg, const float* __restrict__ lbe,
         const int*    __restrict__ dst) {
    int lane = threadIdx.x & 31;
    if (blockIdx.x < BT_BLOCKS) {
        // ---- track points: thread q handles points 2q, 2q+1 ----
        int q = blockIdx.x * blockDim.x + threadIdx.x;
        int ids[2] = {-1, -1};
        float v[2][4];
#pragma unroll
        for (int j = 0; j < 2; j++)
#pragma unroll
            for (int c = 0; c < 4; c++) v[j][c] = 0.f;
        if (q < NP_T / 2) {
            int2 tt = __ldg((const int2*)tid + q);
            ids[0] = tt.x; ids[1] = tt.y;
            float4 p0 = xt[2 * q];
            float4 p1 = xt[2 * q + 1];
            float4 pp[2] = {p0, p1};
#pragma unroll
            for (int j = 0; j < 2; j++) {
                float h[4];
#pragma unroll
                for (int c = 0; c < 4; c++)
                    h[c] = pp[j].x * __ldg(&tW[0 * 4 + c]) + pp[j].y * __ldg(&tW[1 * 4 + c]) +
                           pp[j].z * __ldg(&tW[2 * 4 + c]) + pp[j].w * __ldg(&tW[3 * 4 + c]) + __ldg(&tb[c]);
                float mu = 0.25f * (h[0] + h[1] + h[2] + h[3]);
                float var = 0.f;
#pragma unroll
                for (int c = 0; c < 4; c++) { float d = h[c] - mu; var += d * d; }
                float inv = rsqrtf(var * 0.25f + LN_EPS);
#pragma unroll
                for (int c = 0; c < 4; c++)
                    v[j][c] = fmaxf((h[c] - mu) * inv * __ldg(&tg[c]) + __ldg(&tbe[c]), 0.f);
            }
        }
        // in-thread merge when both points share an id (sorted input)
        if (ids[1] == ids[0]) {
#pragma unroll
            for (int c = 0; c < 4; c++) v[0][c] = fmaxf(v[0][c], v[1][c]);
            ids[1] = -1;
        }
#pragma unroll
        for (int j = 0; j < 2; j++) {
            unsigned msk = __match_any_sync(0xffffffffu, ids[j]);
            unsigned r0 = __reduce_max_sync(msk, __float_as_uint(v[j][0]));
            unsigned r1 = __reduce_max_sync(msk, __float_as_uint(v[j][1]));
            unsigned r2 = __reduce_max_sync(msk, __float_as_uint(v[j][2]));
            unsigned r3 = __reduce_max_sync(msk, __float_as_uint(v[j][3]));
            if (ids[j] >= 0 && lane == (__ffs(msk) - 1)) {
                unsigned int* pool = reinterpret_cast<unsigned int*>(&g_track_pool[ids[j] * 4]);
                atomicMax(&pool[0], r0); atomicMax(&pool[1], r1);
                atomicMax(&pool[2], r2); atomicMax(&pool[3], r3);
            }
        }
    } else if (blockIdx.x < BT_BLOCKS + BL_BLOCKS) {
        // ---- lane points: thread q handles points 2q, 2q+1 (one float4) ----
        int q = (blockIdx.x - BT_BLOCKS) * blockDim.x + threadIdx.x;
        int ids[2] = {-1, -1};
        float v0[2] = {0.f, 0.f}, v1[2] = {0.f, 0.f};
        if (q < NP_L / 2) {
            int2 tt = __ldg((const int2*)lid + q);
            ids[0] = tt.x; ids[1] = tt.y;
            float4 p = xl4[q];
            float px[2] = {p.x, p.z};
            float py[2] = {p.y, p.w};
#pragma unroll
            for (int j = 0; j < 2; j++) {
                float h0 = px[j] * __ldg(&lW[0]) + py[j] * __ldg(&lW[2]) + __ldg(&lb[0]);
                float h1 = px[j] * __ldg(&lW[1]) + py[j] * __ldg(&lW[3]) + __ldg(&lb[1]);
                float mu = 0.5f * (h0 + h1);
                float d0 = h0 - mu, d1 = h1 - mu;
                float inv = rsqrtf(0.5f * (d0 * d0 + d1 * d1) + LN_EPS);
                v0[j] = fmaxf(d0 * inv * __ldg(&lg[0]) + __ldg(&lbe[0]), 0.f);
                v1[j] = fmaxf(d1 * inv * __ldg(&lg[1]) + __ldg(&lbe[1]), 0.f);
            }
        }
        if (ids[1] == ids[0]) {
            v0[0] = fmaxf(v0[0], v0[1]);
            v1[0] = fmaxf(v1[0], v1[1]);
            ids[1] = -1;
        }
#pragma unroll
        for (int j = 0; j < 2; j++) {
            unsigned msk = __match_any_sync(0xffffffffu, ids[j]);
            unsigned r0 = __reduce_max_sync(msk, __float_as_uint(v0[j]));
            unsigned r1 = __reduce_max_sync(msk, __float_as_uint(v1[j]));
            if (ids[j] >= 0 && lane == (__ffs(msk) - 1)) {
                unsigned int* pool = reinterpret_cast<unsigned int*>(&g_lane_pool[ids[j] * 2]);
                atomicMax(&pool[0], r0); atomicMax(&pool[1], r1);
            }
        }
    } else {
        // ---- CSR offsets for dst < N_TRACK (int4) ----
        int q = (blockIdx.x - BT_BLOCKS - BL_BLOCKS) * blockDim.x + threadIdx.x;
        if (q >= E_ATT / 4) return;
        int4 d4 = __ldg((const int4*)dst + q);
        int e0 = 4 * q;
        if (q == 0)
            for (int d = 0; d <= min(d4.x, N_TRACK); ++d) g_off[d] = 0;
        if (d4.x > N_TRACK) return;          // nothing <= N_TRACK left to write
        int v[5];
        v[0] = d4.x; v[1] = d4.y; v[2] = d4.z; v[3] = d4.w;
        v[4] = (e0 + 4 < E_ATT) ? __ldg(&dst[e0 + 4]) : N_ATT;
#pragma unroll
        for (int k = 0; k < 4; ++k) {
            int hi = min(v[k + 1], N_TRACK);
            for (int d = v[k] + 1; d <= hi; ++d) g_off[d] = e0 + k + 1;
        }
    }
}

// ---------------- K3: fused feats + h  (block of 256 handles 64 nodes) ----
__global__ void __launch_bounds__(256)
k_node(const float* __restrict__ tW, const float* __restrict__ tb,
       const float* __restrict__ lW, const float* __restrict__ lb,
       const float* __restrict__ fcW) {
    __shared__ float sf[64 * 10];      // feats for 64 nodes
    __shared__ float sW[10 * 60];      // gat_fc_W
    int t = threadIdx.x;
    int n0 = blockIdx.x * 64;
    for (int i = t; i < 600; i += 256) sW[i] = __ldg(&fcW[i]);
    // feats: 640 items over 256 threads
#pragma unroll
    for (int r = 0; r < 3; r++) {
        int idx = r * 256 + t;
        if (idx >= 640) break;
        int ln = idx / 10, j = idx - ln * 10;
        int n = n0 + ln;
        if (n >= N_ATT) break;
        float acc;
        if (n < N_TRACK) {
            const float* p = &g_track_pool[n * 4];
            acc = __ldg(&tb[j]);
#pragma unroll
            for (int k = 0; k < 4; k++) acc += p[k] * __ldg(&tW[k * 10 + j]);
        } else {
            const float* p = &g_lane_pool[(n - N_TRACK) * 2];
            acc = __ldg(&lb[j]) + p[0] * __ldg(&lW[j]) + p[1] * __ldg(&lW[10 + j]);
        }
        sf[ln * 10 + j] = acc;
    }
    __syncthreads();
    // h: 64 nodes x 15 float4 = 960 items
    float4* __restrict__ h4 = reinterpret_cast<float4*>(g_h);
#pragma unroll
    for (int r = 0; r < 4; r++) {
        int idx = r * 256 + t;
        if (idx >= 960) break;
        int ln = idx / 15, qp = idx - ln * 15;
        int n = n0 + ln;
        if (n >= N_ATT) break;
        const float* f = &sf[ln * 10];
        float4 a = make_float4(0.f, 0.f, 0.f, 0.f);
#pragma unroll
        for (int k = 0; k < 10; k++) {
            float fk = f[k];
            const float* w = &sW[k * 60 + 4 * qp];
            a.x = fmaf(fk, w[0], a.x);
            a.y = fmaf(fk, w[1], a.y);
            a.z = fmaf(fk, w[2], a.z);
            a.w = fmaf(fk, w[3], a.w);
        }
        h4[n * 15 + qp] = a;
    }
}

// ---------------- K4: GAT — warp per dst, lane = head, float2 + x4 ILP ----
__global__ void __launch_bounds__(256)
k_gat(const int* __restrict__ src,
      const float2* __restrict__ al2,
      const float2* __restrict__ ar2,
      const float2* __restrict__ bias2,
      float2* __restrict__ out2) {
    int warp = (blockIdx.x * blockDim.x + threadIdx.x) >> 5;
    int lane = threadIdx.x & 31;
    if (warp >= N_TRACK) return;           // only track destinations are output
    int d = warp;
    int hl = lane < HEADS ? lane : HEADS - 1;   // keep all 32 lanes alive for shfl

    const float2* __restrict__ h2 = reinterpret_cast<const float2*>(g_h);

    int s0 = g_off[d], s1 = g_off[d + 1];
    if (s0 >= s1) {                        // empty segment -> just bias
        if (lane < HEADS) out2[d * 30 + lane] = __ldg(&bias2[lane]);
        return;
    }

    float2 alv = __ldg(&al2[hl]);  alv.x *= LOG2E; alv.y *= LOG2E;
    float2 arv = __ldg(&ar2[hl]);
    float2 hd  = h2[d * 30 + hl];
    float  er  = LOG2E * (hd.x * arv.x + hd.y * arv.y);

    float den = 0.f, a0 = 0.f, a1 = 0.f;

#define PROC(H) { \
    float v = fmaf((H).x, alv.x, fmaf((H).y, alv.y, er)); \
    v = fmaxf(v, NEG_SLOPE * v); \
    float ee = ex2f(v); \
    den += ee; a0 = fmaf(ee, (H).x, a0); a1 = fmaf(ee, (H).y, a1); }
#define PROCM(H, pred) { \
    float v = fmaf((H).x, alv.x, fmaf((H).y, alv.y, er)); \
    v = fmaxf(v, NEG_SLOPE * v); \
    float ee = (pred) ? ex2f(v) : 0.f; \
    den += ee; a0 = fmaf(ee, (H).x, a0); a1 = fmaf(ee, (H).y, a1); }

    for (int base = s0; base < s1; base += 32) {
        int cnt = s1 - base; if (cnt > 32) cnt = 32;
        int my = (lane < cnt) ? __ldg(&src[base + lane]) : 0;   // coalesced batch
        int k = 0;
        for (; k + 4 <= cnt; k += 4) {
            int sA = __shfl_sync(0xffffffffu, my, k);
            int sB = __shfl_sync(0xffffffffu, my, k + 1);
            int sC = __shfl_sync(0xffffffffu, my, k + 2);
            int sD = __shfl_sync(0xffffffffu, my, k + 3);
            float2 hA = h2[sA * 30 + hl];                       // 4 independent LDG.64
            float2 hB = h2[sB * 30 + hl];
            float2 hC = h2[sC * 30 + hl];
            float2 hD = h2[sD * 30 + hl];
            PROC(hA) PROC(hB) PROC(hC) PROC(hD)
        }
        if (k < cnt) {                                          // masked tail group
            int last = cnt - 1;
            int sA = __shfl_sync(0xffffffffu, my, k);
            int sB = __shfl_sync(0xffffffffu, my, min(k + 1, last));
            int sC = __shfl_sync(0xffffffffu, my, min(k + 2, last));
            float2 hA = h2[sA * 30 + hl];
            float2 hB = h2[sB * 30 + hl];
            float2 hC = h2[sC * 30 + hl];
            PROC(hA)
            PROCM(hB, k + 1 < cnt)
            PROCM(hC, k + 2 < cnt)
        }
    }
#undef PROC
#undef PROCM
    if (lane < HEADS) {
        float2 bv = __ldg(&bias2[lane]);
        float r = 1.f / den;
        float2 o;
        o.x = fmaf(a0, r, bv.x);
        o.y = fmaf(a1, r, bv.y);
        out2[d * 30 + lane] = o;
    }
}

// ---------------------------------------------------------------------------
extern "C" void kernel_launch(void* const* d_in, const int* in_sizes, int n_in,
                              void* d_out, int out_size) {
    const float4* track_pts = (const float4*)d_in[0];
    const float4* lane_pts4 = (const float4*)d_in[1];
    const int*    pt_tid    = (const int*)d_in[2];
    const int*    pt_lid    = (const int*)d_in[3];
    const int*    att_src   = (const int*)d_in[4];
    const int*    att_dst   = (const int*)d_in[5];
    const float*  t_mlp_W   = (const float*)d_in[6];
    const float*  t_mlp_b   = (const float*)d_in[7];
    const float*  t_ln_g    = (const float*)d_in[8];
    const float*  t_ln_b    = (const float*)d_in[9];
    const float*  t_out_W   = (const float*)d_in[10];
    const float*  t_out_b   = (const float*)d_in[11];
    const float*  l_mlp_W   = (const float*)d_in[12];
    const float*  l_mlp_b   = (const float*)d_in[13];
    const float*  l_ln_g    = (const float*)d_in[14];
    const float*  l_ln_b    = (const float*)d_in[15];
    const float*  l_out_W   = (const float*)d_in[16];
    const float*  l_out_b   = (const float*)d_in[17];
    const float*  gat_fc_W  = (const float*)d_in[18];
    const float*  gat_al    = (const float*)d_in[19];
    const float*  gat_ar    = (const float*)d_in[20];
    const float*  gat_bias  = (const float*)d_in[21];

    // zero the segment-max pools (graph-capturable memset nodes)
    void* p_track = nullptr; void* p_lane = nullptr;
    cudaGetSymbolAddress(&p_track, g_track_pool);
    cudaGetSymbolAddress(&p_lane,  g_lane_pool);
    cudaMemsetAsync(p_track, 0, N_TRACK * 4 * sizeof(float));
    cudaMemsetAsync(p_lane,  0, N_LANE  * 2 * sizeof(float));

    const int T = 256;
    k_points<<<BT_BLOCKS + BL_BLOCKS + OFF_BLOCKS, T>>>(
        track_pts, pt_tid, t_mlp_W, t_mlp_b, t_ln_g, t_ln_b,
        lane_pts4, pt_lid, l_mlp_W, l_mlp_b, l_ln_g, l_ln_b,
        att_dst);
    k_node<<<(N_ATT + 63) / 64, T>>>(t_out_W, t_out_b, l_out_W, l_out_b, gat_fc_W);
    k_gat<<<(N_TRACK * 32 + T - 1) / T, T>>>(att_src,
                                             (const float2*)gat_al,
                                             (const float2*)gat_ar,
                                             (const float2*)gat_bias,
                                             (float2*)d_out);
}